// round 12
// baseline (speedup 1.0000x reference)
#include <cuda_runtime.h>
#include <cuda_bf16.h>
#include <math_constants.h>

// Problem constants
#define B 2
#define L 1024
#define E 1024
#define H 16
#define NT (B*L)          // 2048 tokens
#define LOG2E 1.4426950408889634f
#define KSPLIT 4

typedef unsigned long long u64;

// -------- scratch (static __device__, no allocations) --------
__device__ float2 g_stats[NT];                   // per-token (mu, rstd)
__device__ float  g_projp[KSPLIT][NT * 240];     // QKV projection partials
__device__ float4 g_Q[B*H*L * 2];                // per (b,h,i): (alpha'*Qr, q2), (qd, -beta')
__device__ float4 g_K[B*H*L * 3];                // per (b,h,j): (Kr, k2), (-2kd, maskpen'), (V, 0)
__device__ float  g_O[NT * H * 3];               // attention output (B,L,H,3)

// ---------------- f32x2 helpers ----------------
__device__ __forceinline__ u64 pk2(float lo, float hi)
{ u64 r; asm("mov.b64 %0, {%1,%2};" : "=l"(r) : "f"(lo), "f"(hi)); return r; }
__device__ __forceinline__ u64 bc2(float v) { return pk2(v, v); }
__device__ __forceinline__ void up2(float &lo, float &hi, u64 v)
{ asm("mov.b64 {%0,%1}, %2;" : "=f"(lo), "=f"(hi) : "l"(v)); }
__device__ __forceinline__ u64 fma2(u64 a, u64 b, u64 c)
{ u64 d; asm("fma.rn.f32x2 %0, %1, %2, %3;" : "=l"(d) : "l"(a), "l"(b), "l"(c)); return d; }
__device__ __forceinline__ u64 add2(u64 a, u64 b)
{ u64 d; asm("add.rn.f32x2 %0, %1, %2;" : "=l"(d) : "l"(a), "l"(b)); return d; }

// ---------------- tf32 helpers ----------------
__device__ __forceinline__ unsigned f2tf32(float a)
{ unsigned r; asm("cvt.rna.tf32.f32 %0, %1;" : "=r"(r) : "f"(a)); return r; }

__device__ __forceinline__ void mma_tf32(float c[4], unsigned a0, unsigned a1,
                                         unsigned a2, unsigned a3,
                                         unsigned b0, unsigned b1)
{
    asm volatile(
        "mma.sync.aligned.m16n8k8.row.col.f32.tf32.tf32.f32 "
        "{%0,%1,%2,%3}, {%4,%5,%6,%7}, {%8,%9}, {%0,%1,%2,%3};"
        : "+f"(c[0]), "+f"(c[1]), "+f"(c[2]), "+f"(c[3])
        : "r"(a0), "r"(a1), "r"(a2), "r"(a3), "r"(b0), "r"(b1));
}

// ============================================================
// K1: LayerNorm STATS ONLY (mu, rstd per token)
// ============================================================
__global__ void __launch_bounds__(256) ln_stats(const float* __restrict__ x)
{
    int t   = blockIdx.x;
    int tid = threadIdx.x;
    const float4* xr = (const float4*)(x + (size_t)t * E);
    float4 v = xr[tid];
    float s  = v.x + v.y + v.z + v.w;
    float ss = v.x*v.x + v.y*v.y + v.z*v.z + v.w*v.w;
    #pragma unroll
    for (int o = 16; o; o >>= 1) {
        s  += __shfl_xor_sync(0xFFFFFFFFu, s,  o);
        ss += __shfl_xor_sync(0xFFFFFFFFu, ss, o);
    }
    __shared__ float sm[8], sm2[8];
    if ((tid & 31) == 0) { sm[tid >> 5] = s; sm2[tid >> 5] = ss; }
    __syncthreads();
    if (tid == 0) {
        float S = 0.f, SS = 0.f;
        #pragma unroll
        for (int i = 0; i < 8; i++) { S += sm[i]; SS += sm2[i]; }
        float mu  = S * (1.0f / E);
        float var = SS * (1.0f / E) - mu * mu;
        g_stats[t] = make_float2(mu, rsqrtf(var + 1e-5f));
    }
}

// ============================================================
// K2: QKV GEMM via 3xTF32 tensor-core MMA, LN fused on stage.
// C[2048x240] = LN(x)[2048x1024] @ Wqkv[1024x240]
// BM=64 BN=48, KSPLIT=4 (z), 128 threads = 4 warps (warp w: rows w*16..+15).
// Frag-order smem: A[rowgroup][lane][12] (8 used: s*4 + {a0,a1,a2,a3}),
// B[nfrag][lane][4] ({b0s0,b1s0,b0s1,b1s1}). hi/lo tf32 split per element.
// ============================================================
__global__ void __launch_bounds__(128) qkv_gemm(const float* __restrict__ x,
                                                const float* __restrict__ gamma,
                                                const float* __restrict__ beta,
                                                const float* __restrict__ W)
{
    __shared__ unsigned AH[4*32*12], AL[4*32*12];   // 6KB each
    __shared__ unsigned BH[6*32*4],  BL[6*32*4];    // 3KB each

    int bm = blockIdx.x * 64;
    int bn = blockIdx.y * 48;
    int kh = blockIdx.z;
    int t  = threadIdx.x;
    int w  = t >> 5, l = t & 31;

    float c[6][4];
    #pragma unroll
    for (int f = 0; f < 6; f++)
        #pragma unroll
        for (int i = 0; i < 4; i++) c[f][i] = 0.f;

    // A staging map: thread t stages rows (t>>2) and (t>>2)+32, k-quartet (t&3)*4
    int arow = t >> 2;
    int akc  = (t & 3) * 4;
    int areg = (((akc & 7) >= 4) ? 2 : 0) + ((akc >= 8) ? 4 : 0);

    // B staging map: thread t stages k=(t>>3), n=(t&7)*6 .. +5
    int bkk  = t >> 3;
    int bn6  = (t & 7) * 6;
    int bslot = ((bkk >= 8) ? 2 : 0) + (((bkk & 7) >= 4) ? 1 : 0);

    float2 st0 = g_stats[bm + arow];
    float2 st1 = g_stats[bm + arow + 32];

    const int KQ = 1024 / KSPLIT;        // 256
    for (int k0 = kh * KQ; k0 < kh * KQ + KQ; k0 += 16) {
        float4 ga = *(const float4*)(gamma + k0 + akc);
        float4 bt = *(const float4*)(beta  + k0 + akc);
        #pragma unroll
        for (int i = 0; i < 2; i++) {
            int row = arow + 32 * i;
            float4 av = *(const float4*)(x + (size_t)(bm + row) * E + k0 + akc);
            float mu = i ? st1.x : st0.x;
            float rs = i ? st1.y : st0.y;
            float e[4];
            e[0] = fmaf((av.x - mu) * rs, ga.x, bt.x);
            e[1] = fmaf((av.y - mu) * rs, ga.y, bt.y);
            e[2] = fmaf((av.z - mu) * rs, ga.z, bt.z);
            e[3] = fmaf((av.w - mu) * rs, ga.w, bt.w);
            int rg   = row >> 4;
            int r16  = row & 15;
            int reg  = areg + ((r16 >= 8) ? 1 : 0);
            int lb   = (r16 & 7) * 4;
            #pragma unroll
            for (int j = 0; j < 4; j++) {
                unsigned hi = f2tf32(e[j]);
                unsigned lo = f2tf32(e[j] - __uint_as_float(hi));
                int idx = (rg * 32 + lb + j) * 12 + reg;
                AH[idx] = hi;
                AL[idx] = lo;
            }
        }
        {
            const float* wp = W + (size_t)(k0 + bkk) * 240 + bn + bn6;
            #pragma unroll
            for (int j = 0; j < 6; j++) {
                float v = wp[j];
                unsigned hi = f2tf32(v);
                unsigned lo = f2tf32(v - __uint_as_float(hi));
                int n  = bn6 + j;
                int fr = n >> 3;
                int ln = (n & 7) * 4 + (bkk & 3);
                int idx = (fr * 32 + ln) * 4 + bslot;
                BH[idx] = hi;
                BL[idx] = lo;
            }
        }
        __syncthreads();

        const uint4* ahp = (const uint4*)&AH[(w * 32 + l) * 12];
        const uint4* alp = (const uint4*)&AL[(w * 32 + l) * 12];
        uint4 ah0 = ahp[0], ah1 = ahp[1];
        uint4 al0 = alp[0], al1 = alp[1];
        #pragma unroll
        for (int f = 0; f < 6; f++) {
            uint4 bh = *(const uint4*)&BH[(f * 32 + l) * 4];
            uint4 bl = *(const uint4*)&BL[(f * 32 + l) * 4];
            // k-step 0
            mma_tf32(c[f], ah0.x, ah0.y, ah0.z, ah0.w, bh.x, bh.y);
            mma_tf32(c[f], al0.x, al0.y, al0.z, al0.w, bh.x, bh.y);
            mma_tf32(c[f], ah0.x, ah0.y, ah0.z, ah0.w, bl.x, bl.y);
            // k-step 1
            mma_tf32(c[f], ah1.x, ah1.y, ah1.z, ah1.w, bh.z, bh.w);
            mma_tf32(c[f], al1.x, al1.y, al1.z, al1.w, bh.z, bh.w);
            mma_tf32(c[f], ah1.x, ah1.y, ah1.z, ah1.w, bl.z, bl.w);
        }
        __syncthreads();
    }

    // epilogue: C frag layout c0:(r=l/4, n=2(l&3)) c1:+1 c2,c3: r+8
    float* out = g_projp[kh];
    int row0 = bm + w * 16 + (l >> 2);
    int colb = bn + 2 * (l & 3);
    #pragma unroll
    for (int f = 0; f < 6; f++) {
        int col = colb + f * 8;
        *(float2*)&out[(size_t)row0 * 240 + col]       = make_float2(c[f][0], c[f][1]);
        *(float2*)&out[(size_t)(row0 + 8) * 240 + col] = make_float2(c[f][2], c[f][3]);
    }
}

// ============================================================
// K2b: rotate + translate + pack per (token, head)   (proven R10)
// ============================================================
__device__ __forceinline__ float softplus_f(float x)
{
    return (x > 20.f) ? x : log1pf(__expf(x));
}

__global__ void __launch_bounds__(256) pack_kernel(const float* __restrict__ rot,
                                                   const float* __restrict__ trans,
                                                   const unsigned char* __restrict__ mask,
                                                   const float* __restrict__ r_scale,
                                                   const float* __restrict__ d_scale)
{
    int gid = blockIdx.x * blockDim.x + threadIdx.x;
    if (gid >= NT * H) return;
    int t = gid >> 4;
    int h = gid & 15;

    float R[9];
    #pragma unroll
    for (int i = 0; i < 9; i++) R[i] = rot[t*9 + i];
    float T0 = trans[t*3+0], T1 = trans[t*3+1], T2 = trans[t*3+2];

    float y[5][3];
    #pragma unroll
    for (int f = 0; f < 5; f++) {
        int o = f*48 + h*3;
        float v0 = 0.f, v1 = 0.f, v2 = 0.f;
        #pragma unroll
        for (int q = 0; q < KSPLIT; q++) {
            const float* P = g_projp[q] + (size_t)t * 240;
            v0 += P[o+0]; v1 += P[o+1]; v2 += P[o+2];
        }
        y[f][0] = R[0]*v0 + R[1]*v1 + R[2]*v2;
        y[f][1] = R[3]*v0 + R[4]*v1 + R[5]*v2;
        y[f][2] = R[6]*v0 + R[7]*v1 + R[8]*v2;
    }
    const float scale = 0.5773502691896258f;      // 3^-0.5
    float alpha = softplus_f(r_scale[h]) * scale * LOG2E;
    float nbeta = -softplus_f(d_scale[h]) * scale * LOG2E;

    float qd0 = y[2][0] + T0, qd1 = y[2][1] + T1, qd2 = y[2][2] + T2;
    float q2  = qd0*qd0 + qd1*qd1 + qd2*qd2;
    float kd0 = y[3][0] + T0, kd1 = y[3][1] + T1, kd2 = y[3][2] + T2;
    float k2  = kd0*kd0 + kd1*kd1 + kd2*kd2;

    int b = t >> 10, l = t & 1023;
    int base = (b*H + h) * L + l;

    g_Q[base*2 + 0] = make_float4(alpha*y[0][0], alpha*y[0][1], alpha*y[0][2], q2);
    g_Q[base*2 + 1] = make_float4(qd0, qd1, qd2, nbeta);

    float mpen = mask[t] ? -2.0e9f : 0.f;   // log2 units; EX2 -> 0
    g_K[base*3 + 0] = make_float4(y[1][0], y[1][1], y[1][2], k2);
    g_K[base*3 + 1] = make_float4(-2.f*kd0, -2.f*kd1, -2.f*kd2, mpen);
    g_K[base*3 + 2] = make_float4(y[4][0], y[4][1], y[4][2], 0.f);
}

// ============================================================
// K3: flash attention, row-pair f32x2, no online max.  (proven R10)
// 8 warps x 4 rows; grid (B*H, L/32); 4 blocks/SM (regs 64).
// ============================================================
__global__ void __launch_bounds__(256, 4) attn_kernel()
{
    __shared__ float4 sk[L * 3];   // 49152 bytes

    int bh    = blockIdx.x;
    int itile = blockIdx.y;

    const float4* Ksrc = g_K + (size_t)bh * L * 3;
    #pragma unroll
    for (int i = 0; i < 12; i++) sk[threadIdx.x + 256 * i] = Ksrc[threadIdx.x + 256 * i];
    __syncthreads();

    int warp = threadIdx.x >> 5, lane = threadIdx.x & 31;
    int rbase = itile * 32 + warp * 4;

    const float4* Qsrc = g_Q + (size_t)(bh * L + rbase) * 2;
    u64 QRX[2], QRY[2], QRZ[2], Q2[2], QDX[2], QDY[2], QDZ[2];
    u64 S[2], A0[2], A1[2], A2[2];
    u64 NB;
    #pragma unroll
    for (int p = 0; p < 2; p++) {
        float4 alo = Qsrc[(2*p)*2],     blo = Qsrc[(2*p)*2 + 1];
        float4 ahi = Qsrc[(2*p+1)*2],   bhi = Qsrc[(2*p+1)*2 + 1];
        QRX[p] = pk2(alo.x, ahi.x); QRY[p] = pk2(alo.y, ahi.y);
        QRZ[p] = pk2(alo.z, ahi.z); Q2 [p] = pk2(alo.w, ahi.w);
        QDX[p] = pk2(blo.x, bhi.x); QDY[p] = pk2(blo.y, bhi.y);
        QDZ[p] = pk2(blo.z, bhi.z);
        if (p == 0) NB = bc2(blo.w);
        S[p] = 0ull; A0[p] = 0ull; A1[p] = 0ull; A2[p] = 0ull;
    }

    #pragma unroll 4
    for (int jj = 0; jj < 32; jj++) {
        int j = jj * 32 + lane;
        float4 kr = sk[j*3 + 0];
        float4 kd = sk[j*3 + 1];
        float4 vv = sk[j*3 + 2];
        u64 KRX = bc2(kr.x), KRY = bc2(kr.y), KRZ = bc2(kr.z), KRW = bc2(kr.w);
        u64 KDX = bc2(kd.x), KDY = bc2(kd.y), KDZ = bc2(kd.z), KDW = bc2(kd.w);
        u64 VX  = bc2(vv.x), VY  = bc2(vv.y), VZ  = bc2(vv.z);
        #pragma unroll
        for (int p = 0; p < 2; p++) {
            u64 t1 = fma2(QRX[p], KRX, KDW);
            t1 = fma2(QRY[p], KRY, t1);
            t1 = fma2(QRZ[p], KRZ, t1);
            u64 d2 = add2(Q2[p], KRW);
            d2 = fma2(QDX[p], KDX, d2);
            d2 = fma2(QDY[p], KDY, d2);
            d2 = fma2(QDZ[p], KDZ, d2);
            float d2a, d2b;
            up2(d2a, d2b, d2);
            float da, db, pa, pb;
            float ada = fabsf(d2a), adb = fabsf(d2b);
            asm("sqrt.approx.f32 %0, %1;" : "=f"(da) : "f"(ada));
            asm("sqrt.approx.f32 %0, %1;" : "=f"(db) : "f"(adb));
            u64 DD = pk2(da, db);
            u64 ARG = fma2(NB, DD, t1);
            float arga, argb;
            up2(arga, argb, ARG);
            asm("ex2.approx.f32 %0, %1;" : "=f"(pa) : "f"(arga));
            asm("ex2.approx.f32 %0, %1;" : "=f"(pb) : "f"(argb));
            u64 P = pk2(pa, pb);
            S [p] = add2(S[p], P);
            A0[p] = fma2(P, VX, A0[p]);
            A1[p] = fma2(P, VY, A1[p]);
            A2[p] = fma2(P, VZ, A2[p]);
        }
    }

    int b = bh >> 4, h = bh & 15;
    #pragma unroll
    for (int p = 0; p < 2; p++) {
        float s0, s1, x0, x1, y0, y1, z0, z1;
        up2(s0, s1, S[p]); up2(x0, x1, A0[p]); up2(y0, y1, A1[p]); up2(z0, z1, A2[p]);
        #pragma unroll
        for (int o = 16; o; o >>= 1) {
            s0 += __shfl_xor_sync(0xFFFFFFFFu, s0, o);
            x0 += __shfl_xor_sync(0xFFFFFFFFu, x0, o);
            y0 += __shfl_xor_sync(0xFFFFFFFFu, y0, o);
            z0 += __shfl_xor_sync(0xFFFFFFFFu, z0, o);
            s1 += __shfl_xor_sync(0xFFFFFFFFu, s1, o);
            x1 += __shfl_xor_sync(0xFFFFFFFFu, x1, o);
            y1 += __shfl_xor_sync(0xFFFFFFFFu, y1, o);
            z1 += __shfl_xor_sync(0xFFFFFFFFu, z1, o);
        }
        if (lane == 0) {
            float inv0, inv1;
            asm("rcp.approx.f32 %0, %1;" : "=f"(inv0) : "f"(s0));
            asm("rcp.approx.f32 %0, %1;" : "=f"(inv1) : "f"(s1));
            int row0 = rbase + 2*p;
            float* op0 = g_O + ((size_t)(b * L + row0) * H + h) * 3;
            float* op1 = g_O + ((size_t)(b * L + row0 + 1) * H + h) * 3;
            op0[0] = x0 * inv0; op0[1] = y0 * inv0; op0[2] = z0 * inv0;
            op1[0] = x1 * inv1; op1[1] = y1 * inv1; op1[2] = z1 * inv1;
        }
    }
}

// ============================================================
// K4: rotate back (R^T) + output GEMM (48 -> 1024) + bias, f32x2
// 16 tokens per block, 256 threads.  (proven R10)
// ============================================================
__global__ void __launch_bounds__(256) out_kernel(const float* __restrict__ rot,
                                                  const float* __restrict__ Wout,
                                                  const float* __restrict__ bout,
                                                  float* __restrict__ out)
{
    __shared__ float so[48][16];
    int t0  = blockIdx.x * 16;
    int tid = threadIdx.x;

    {
        int tt = tid >> 4, h = tid & 15;
        int t = t0 + tt;
        const float* op = g_O + ((size_t)t * H + h) * 3;
        float R0 = rot[t*9+0], R1 = rot[t*9+1], R2 = rot[t*9+2];
        float R3 = rot[t*9+3], R4 = rot[t*9+4], R5 = rot[t*9+5];
        float R6 = rot[t*9+6], R7 = rot[t*9+7], R8 = rot[t*9+8];
        float o0 = op[0], o1 = op[1], o2 = op[2];
        so[h*3+0][tt] = R0*o0 + R3*o1 + R6*o2;
        so[h*3+1][tt] = R1*o0 + R4*o1 + R7*o2;
        so[h*3+2][tt] = R2*o0 + R5*o1 + R8*o2;
    }
    __syncthreads();

    int e0 = tid;
    u64 acc[8][4];
    #pragma unroll
    for (int c = 0; c < 4; c++) {
        float bb = bout[e0 + 256*c];
        u64 bb2 = bc2(bb);
        #pragma unroll
        for (int tp = 0; tp < 8; tp++) acc[tp][c] = bb2;
    }

    #pragma unroll 4
    for (int k = 0; k < 48; k++) {
        u64 w2[4];
        #pragma unroll
        for (int c = 0; c < 4; c++) w2[c] = bc2(Wout[(size_t)k*E + e0 + 256*c]);
        const u64* sop = (const u64*)&so[k][0];
        #pragma unroll
        for (int tp = 0; tp < 8; tp++) {
            u64 sv = sop[tp];
            acc[tp][0] = fma2(sv, w2[0], acc[tp][0]);
            acc[tp][1] = fma2(sv, w2[1], acc[tp][1]);
            acc[tp][2] = fma2(sv, w2[2], acc[tp][2]);
            acc[tp][3] = fma2(sv, w2[3], acc[tp][3]);
        }
    }
    #pragma unroll
    for (int tp = 0; tp < 8; tp++) {
        float* orow0 = out + (size_t)(t0 + 2*tp) * E;
        float* orow1 = out + (size_t)(t0 + 2*tp + 1) * E;
        #pragma unroll
        for (int c = 0; c < 4; c++) {
            float lo, hi;
            up2(lo, hi, acc[tp][c]);
            orow0[e0 + 256*c] = lo;
            orow1[e0 + 256*c] = hi;
        }
    }
}

// ============================================================
extern "C" void kernel_launch(void* const* d_in, const int* in_sizes, int n_in,
                              void* d_out, int out_size)
{
    const float*         x       = (const float*)d_in[0];
    const float*         rot     = (const float*)d_in[1];
    const float*         trans   = (const float*)d_in[2];
    const unsigned char* mask    = (const unsigned char*)d_in[3];
    const float*         Wqkv    = (const float*)d_in[4];
    const float*         Wout    = (const float*)d_in[5];
    const float*         bout    = (const float*)d_in[6];
    const float*         gamma   = (const float*)d_in[7];
    const float*         beta    = (const float*)d_in[8];
    const float*         r_scale = (const float*)d_in[9];
    const float*         d_scale = (const float*)d_in[10];
    float* out = (float*)d_out;

    ln_stats<<<NT, 256>>>(x);
    qkv_gemm<<<dim3(NT/64, 5, KSPLIT), 128>>>(x, gamma, beta, Wqkv);
    pack_kernel<<<(NT*H + 255)/256, 256>>>(rot, trans, mask, r_scale, d_scale);
    attn_kernel<<<dim3(B*H, L/32), 256>>>();
    out_kernel<<<NT/16, 256>>>(rot, Wout, bout, out);
}

// round 13
// speedup vs baseline: 1.1454x; 1.1454x over previous
#include <cuda_runtime.h>
#include <cuda_bf16.h>
#include <math_constants.h>

// Problem constants
#define B 2
#define L 1024
#define E 1024
#define H 16
#define NT (B*L)          // 2048 tokens
#define LOG2E 1.4426950408889634f
#define KSPLIT 4

typedef unsigned long long u64;

// -------- scratch (static __device__, no allocations) --------
__device__ float2 g_stats[NT];                   // per-token (mu, rstd)
__device__ float  g_projp[KSPLIT][NT * 240];     // QKV projection partials
__device__ float4 g_Q[B*H*L * 2];                // per (b,h,i): (alpha'*Qr, q2), (qd, -beta')
__device__ float4 g_K[B*H*L * 3];                // per (b,h,j): (Kr, k2), (-2kd, maskpen'), (V, 0)
__device__ float  g_O[NT * H * 3];               // attention output (B,L,H,3)

// ---------------- f32x2 helpers ----------------
__device__ __forceinline__ u64 pk2(float lo, float hi)
{ u64 r; asm("mov.b64 %0, {%1,%2};" : "=l"(r) : "f"(lo), "f"(hi)); return r; }
__device__ __forceinline__ u64 bc2(float v) { return pk2(v, v); }
__device__ __forceinline__ void up2(float &lo, float &hi, u64 v)
{ asm("mov.b64 {%0,%1}, %2;" : "=f"(lo), "=f"(hi) : "l"(v)); }
__device__ __forceinline__ u64 fma2(u64 a, u64 b, u64 c)
{ u64 d; asm("fma.rn.f32x2 %0, %1, %2, %3;" : "=l"(d) : "l"(a), "l"(b), "l"(c)); return d; }
__device__ __forceinline__ u64 add2(u64 a, u64 b)
{ u64 d; asm("add.rn.f32x2 %0, %1, %2;" : "=l"(d) : "l"(a), "l"(b)); return d; }

// ============================================================
// K1: LayerNorm STATS, warp-per-token (8 tokens/block, no smem)
// ============================================================
__global__ void __launch_bounds__(256) ln_stats(const float* __restrict__ x)
{
    int warp = threadIdx.x >> 5, lane = threadIdx.x & 31;
    int t = blockIdx.x * 8 + warp;
    const float4* xr = (const float4*)(x + (size_t)t * E);
    float s = 0.f, ss = 0.f;
    #pragma unroll
    for (int i = 0; i < 8; i++) {
        float4 v = xr[lane + 32 * i];
        s  += v.x + v.y + v.z + v.w;
        ss += v.x*v.x + v.y*v.y + v.z*v.z + v.w*v.w;
    }
    #pragma unroll
    for (int o = 16; o; o >>= 1) {
        s  += __shfl_xor_sync(0xFFFFFFFFu, s,  o);
        ss += __shfl_xor_sync(0xFFFFFFFFu, ss, o);
    }
    if (lane == 0) {
        float mu  = s * (1.0f / E);
        float var = ss * (1.0f / E) - mu * mu;
        g_stats[t] = make_float2(mu, rsqrtf(var + 1e-5f));
    }
}

// ============================================================
// K2: QKV GEMM, f32x2, conflict-free staging, LN fused,
// register-prefetch double-buffered pipeline (1 sync/tile).
// C[2048x240] = LN(x)[2048x1024] @ Wqkv[1024x240]
// BM=64 BN=48, KSPLIT=4 (z), 128 threads, micro 8 rows x 3 cols.
// ============================================================
__global__ void __launch_bounds__(128) qkv_gemm(const float* __restrict__ x,
                                                const float* __restrict__ gamma,
                                                const float* __restrict__ beta,
                                                const float* __restrict__ W)
{
    __shared__ float As[2][16 * 64];   // 2 x 4KB
    __shared__ float Bs[2][16 * 98];   // 2 x 6.27KB

    int bm = blockIdx.x * 64;
    int bn = blockIdx.y * 48;
    int kh = blockIdx.z;
    int t  = threadIdx.x;
    int ty2 = (t >> 4) * 2;
    int tx = t & 15;

    u64 acc[4][3];
    #pragma unroll
    for (int i = 0; i < 4; i++)
        #pragma unroll
        for (int c = 0; c < 3; c++) acc[i][c] = 0ull;

    // staging maps
    int arow = t >> 2;
    int akc  = (t & 3) * 4;
    int aq2  = (t & 3) << 1;
    int bk   = t >> 3;
    int bcf  = (t & 7) * 6;

    const float* xp0 = x + (size_t)(bm + arow) * E + akc;
    const float* xp1 = x + (size_t)(bm + arow + 32) * E + akc;
    const float* wpb = W + (size_t)bk * 240 + bn + bcf;

    float2 st0 = g_stats[bm + arow];
    float2 st1 = g_stats[bm + arow + 32];

    int gofs0 = (((arow >> 2)        ^ aq2) << 2) + (arow & 3);
    int gofs1 = ((((arow + 32) >> 2) ^ aq2) << 2) + ((arow + 32) & 3);

    const int k0base = kh * (1024 / KSPLIT);       // 256-wide K window
    const int NTILE = (1024 / KSPLIT) / 16;        // 16

    // prefetch registers
    float4 av0, av1, ga, bt;
    float2 b0, b1, b2;

    // ---- load tile 0 ----
    {
        int k0 = k0base;
        av0 = *(const float4*)(xp0 + k0);
        av1 = *(const float4*)(xp1 + k0);
        ga  = *(const float4*)(gamma + k0 + akc);
        bt  = *(const float4*)(beta  + k0 + akc);
        const float* wp = wpb + (size_t)k0 * 240;
        b0 = *(const float2*)(wp + 0);
        b1 = *(const float2*)(wp + 2);
        b2 = *(const float2*)(wp + 4);
    }
    // ---- store tile 0 into buf 0 ----
    {
        float* A = As[0];
        float mu = st0.x, rs = st0.y;
        A[(akc + 0) * 64 + gofs0] = fmaf((av0.x - mu) * rs, ga.x, bt.x);
        A[(akc + 1) * 64 + gofs0] = fmaf((av0.y - mu) * rs, ga.y, bt.y);
        A[(akc + 2) * 64 + gofs0] = fmaf((av0.z - mu) * rs, ga.z, bt.z);
        A[(akc + 3) * 64 + gofs0] = fmaf((av0.w - mu) * rs, ga.w, bt.w);
        mu = st1.x; rs = st1.y;
        A[(akc + 0) * 64 + gofs1] = fmaf((av1.x - mu) * rs, ga.x, bt.x);
        A[(akc + 1) * 64 + gofs1] = fmaf((av1.y - mu) * rs, ga.y, bt.y);
        A[(akc + 2) * 64 + gofs1] = fmaf((av1.z - mu) * rs, ga.z, bt.z);
        A[(akc + 3) * 64 + gofs1] = fmaf((av1.w - mu) * rs, ga.w, bt.w);
        u64* bs = (u64*)&Bs[0][bk * 98 + bcf * 2];
        bs[0] = bc2(b0.x); bs[1] = bc2(b0.y);
        bs[2] = bc2(b1.x); bs[3] = bc2(b1.y);
        bs[4] = bc2(b2.x); bs[5] = bc2(b2.y);
    }
    __syncthreads();

    for (int it = 0; it < NTILE; it++) {
        // prefetch next tile to registers BEFORE compute
        if (it + 1 < NTILE) {
            int kn = k0base + (it + 1) * 16;
            av0 = *(const float4*)(xp0 + kn);
            av1 = *(const float4*)(xp1 + kn);
            ga  = *(const float4*)(gamma + kn + akc);
            bt  = *(const float4*)(beta  + kn + akc);
            const float* wp = wpb + (size_t)kn * 240;
            b0 = *(const float2*)(wp + 0);
            b1 = *(const float2*)(wp + 2);
            b2 = *(const float2*)(wp + 4);
        }

        const float* Ab = As[it & 1];
        const float* Bb = Bs[it & 1];
        #pragma unroll
        for (int kk = 0; kk < 16; kk++) {
            const int q2s = (kk >> 2) << 1;
            const float* arow_p = &Ab[kk * 64 + ((ty2 ^ q2s) << 2)];
            ulonglong2 a01 = *(const ulonglong2*)(arow_p);
            ulonglong2 a23 = *(const ulonglong2*)(arow_p + 4);
            const float* brow = &Bb[kk * 98 + tx * 6];
            u64 w0 = *(const u64*)(brow + 0);
            u64 w1 = *(const u64*)(brow + 2);
            u64 w2 = *(const u64*)(brow + 4);
            acc[0][0]=fma2(a01.x,w0,acc[0][0]); acc[0][1]=fma2(a01.x,w1,acc[0][1]); acc[0][2]=fma2(a01.x,w2,acc[0][2]);
            acc[1][0]=fma2(a01.y,w0,acc[1][0]); acc[1][1]=fma2(a01.y,w1,acc[1][1]); acc[1][2]=fma2(a01.y,w2,acc[1][2]);
            acc[2][0]=fma2(a23.x,w0,acc[2][0]); acc[2][1]=fma2(a23.x,w1,acc[2][1]); acc[2][2]=fma2(a23.x,w2,acc[2][2]);
            acc[3][0]=fma2(a23.y,w0,acc[3][0]); acc[3][1]=fma2(a23.y,w1,acc[3][1]); acc[3][2]=fma2(a23.y,w2,acc[3][2]);
        }

        if (it + 1 < NTILE) {
            int nb = (it + 1) & 1;
            float* A = As[nb];
            float mu = st0.x, rs = st0.y;
            A[(akc + 0) * 64 + gofs0] = fmaf((av0.x - mu) * rs, ga.x, bt.x);
            A[(akc + 1) * 64 + gofs0] = fmaf((av0.y - mu) * rs, ga.y, bt.y);
            A[(akc + 2) * 64 + gofs0] = fmaf((av0.z - mu) * rs, ga.z, bt.z);
            A[(akc + 3) * 64 + gofs0] = fmaf((av0.w - mu) * rs, ga.w, bt.w);
            mu = st1.x; rs = st1.y;
            A[(akc + 0) * 64 + gofs1] = fmaf((av1.x - mu) * rs, ga.x, bt.x);
            A[(akc + 1) * 64 + gofs1] = fmaf((av1.y - mu) * rs, ga.y, bt.y);
            A[(akc + 2) * 64 + gofs1] = fmaf((av1.z - mu) * rs, ga.z, bt.z);
            A[(akc + 3) * 64 + gofs1] = fmaf((av1.w - mu) * rs, ga.w, bt.w);
            u64* bs = (u64*)&Bs[nb][bk * 98 + bcf * 2];
            bs[0] = bc2(b0.x); bs[1] = bc2(b0.y);
            bs[2] = bc2(b1.x); bs[3] = bc2(b1.y);
            bs[4] = bc2(b2.x); bs[5] = bc2(b2.y);
            __syncthreads();
        }
    }

    float* out = g_projp[kh];
    int ty = t >> 4;
    #pragma unroll
    for (int i = 0; i < 4; i++) {
        int row = bm + ty * 8 + 2 * i;
        #pragma unroll
        for (int c = 0; c < 3; c++) {
            float lo, hi;
            up2(lo, hi, acc[i][c]);
            int col = bn + tx * 3 + c;
            out[(size_t)row * 240 + col]       = lo;
            out[(size_t)(row + 1) * 240 + col] = hi;
        }
    }
}

// ============================================================
// K2b: rotate + translate + pack per (token, head)   (proven R10)
// ============================================================
__device__ __forceinline__ float softplus_f(float x)
{
    return (x > 20.f) ? x : log1pf(__expf(x));
}

__global__ void __launch_bounds__(256) pack_kernel(const float* __restrict__ rot,
                                                   const float* __restrict__ trans,
                                                   const unsigned char* __restrict__ mask,
                                                   const float* __restrict__ r_scale,
                                                   const float* __restrict__ d_scale)
{
    int gid = blockIdx.x * blockDim.x + threadIdx.x;
    if (gid >= NT * H) return;
    int t = gid >> 4;
    int h = gid & 15;

    float R[9];
    #pragma unroll
    for (int i = 0; i < 9; i++) R[i] = rot[t*9 + i];
    float T0 = trans[t*3+0], T1 = trans[t*3+1], T2 = trans[t*3+2];

    float y[5][3];
    #pragma unroll
    for (int f = 0; f < 5; f++) {
        int o = f*48 + h*3;
        float v0 = 0.f, v1 = 0.f, v2 = 0.f;
        #pragma unroll
        for (int q = 0; q < KSPLIT; q++) {
            const float* P = g_projp[q] + (size_t)t * 240;
            v0 += P[o+0]; v1 += P[o+1]; v2 += P[o+2];
        }
        y[f][0] = R[0]*v0 + R[1]*v1 + R[2]*v2;
        y[f][1] = R[3]*v0 + R[4]*v1 + R[5]*v2;
        y[f][2] = R[6]*v0 + R[7]*v1 + R[8]*v2;
    }
    const float scale = 0.5773502691896258f;      // 3^-0.5
    float alpha = softplus_f(r_scale[h]) * scale * LOG2E;
    float nbeta = -softplus_f(d_scale[h]) * scale * LOG2E;

    float qd0 = y[2][0] + T0, qd1 = y[2][1] + T1, qd2 = y[2][2] + T2;
    float q2  = qd0*qd0 + qd1*qd1 + qd2*qd2;
    float kd0 = y[3][0] + T0, kd1 = y[3][1] + T1, kd2 = y[3][2] + T2;
    float k2  = kd0*kd0 + kd1*kd1 + kd2*kd2;

    int b = t >> 10, l = t & 1023;
    int base = (b*H + h) * L + l;

    g_Q[base*2 + 0] = make_float4(alpha*y[0][0], alpha*y[0][1], alpha*y[0][2], q2);
    g_Q[base*2 + 1] = make_float4(qd0, qd1, qd2, nbeta);

    float mpen = mask[t] ? -2.0e9f : 0.f;   // log2 units; EX2 -> 0
    g_K[base*3 + 0] = make_float4(y[1][0], y[1][1], y[1][2], k2);
    g_K[base*3 + 1] = make_float4(-2.f*kd0, -2.f*kd1, -2.f*kd2, mpen);
    g_K[base*3 + 2] = make_float4(y[4][0], y[4][1], y[4][2], 0.f);
}

// ============================================================
// K3: flash attention, row-pair f32x2, no online max.  (proven R10)
// 8 warps x 4 rows; grid (B*H, L/32); 4 blocks/SM (regs 64).
// ============================================================
__global__ void __launch_bounds__(256, 4) attn_kernel()
{
    __shared__ float4 sk[L * 3];   // 49152 bytes

    int bh    = blockIdx.x;
    int itile = blockIdx.y;

    const float4* Ksrc = g_K + (size_t)bh * L * 3;
    #pragma unroll
    for (int i = 0; i < 12; i++) sk[threadIdx.x + 256 * i] = Ksrc[threadIdx.x + 256 * i];
    __syncthreads();

    int warp = threadIdx.x >> 5, lane = threadIdx.x & 31;
    int rbase = itile * 32 + warp * 4;

    const float4* Qsrc = g_Q + (size_t)(bh * L + rbase) * 2;
    u64 QRX[2], QRY[2], QRZ[2], Q2[2], QDX[2], QDY[2], QDZ[2];
    u64 S[2], A0[2], A1[2], A2[2];
    u64 NB;
    #pragma unroll
    for (int p = 0; p < 2; p++) {
        float4 alo = Qsrc[(2*p)*2],     blo = Qsrc[(2*p)*2 + 1];
        float4 ahi = Qsrc[(2*p+1)*2],   bhi = Qsrc[(2*p+1)*2 + 1];
        QRX[p] = pk2(alo.x, ahi.x); QRY[p] = pk2(alo.y, ahi.y);
        QRZ[p] = pk2(alo.z, ahi.z); Q2 [p] = pk2(alo.w, ahi.w);
        QDX[p] = pk2(blo.x, bhi.x); QDY[p] = pk2(blo.y, bhi.y);
        QDZ[p] = pk2(blo.z, bhi.z);
        if (p == 0) NB = bc2(blo.w);
        S[p] = 0ull; A0[p] = 0ull; A1[p] = 0ull; A2[p] = 0ull;
    }

    #pragma unroll 4
    for (int jj = 0; jj < 32; jj++) {
        int j = jj * 32 + lane;
        float4 kr = sk[j*3 + 0];
        float4 kd = sk[j*3 + 1];
        float4 vv = sk[j*3 + 2];
        u64 KRX = bc2(kr.x), KRY = bc2(kr.y), KRZ = bc2(kr.z), KRW = bc2(kr.w);
        u64 KDX = bc2(kd.x), KDY = bc2(kd.y), KDZ = bc2(kd.z), KDW = bc2(kd.w);
        u64 VX  = bc2(vv.x), VY  = bc2(vv.y), VZ  = bc2(vv.z);
        #pragma unroll
        for (int p = 0; p < 2; p++) {
            u64 t1 = fma2(QRX[p], KRX, KDW);
            t1 = fma2(QRY[p], KRY, t1);
            t1 = fma2(QRZ[p], KRZ, t1);
            u64 d2 = add2(Q2[p], KRW);
            d2 = fma2(QDX[p], KDX, d2);
            d2 = fma2(QDY[p], KDY, d2);
            d2 = fma2(QDZ[p], KDZ, d2);
            float d2a, d2b;
            up2(d2a, d2b, d2);
            float da, db, pa, pb;
            float ada = fabsf(d2a), adb = fabsf(d2b);
            asm("sqrt.approx.f32 %0, %1;" : "=f"(da) : "f"(ada));
            asm("sqrt.approx.f32 %0, %1;" : "=f"(db) : "f"(adb));
            u64 DD = pk2(da, db);
            u64 ARG = fma2(NB, DD, t1);
            float arga, argb;
            up2(arga, argb, ARG);
            asm("ex2.approx.f32 %0, %1;" : "=f"(pa) : "f"(arga));
            asm("ex2.approx.f32 %0, %1;" : "=f"(pb) : "f"(argb));
            u64 P = pk2(pa, pb);
            S [p] = add2(S[p], P);
            A0[p] = fma2(P, VX, A0[p]);
            A1[p] = fma2(P, VY, A1[p]);
            A2[p] = fma2(P, VZ, A2[p]);
        }
    }

    int b = bh >> 4, h = bh & 15;
    #pragma unroll
    for (int p = 0; p < 2; p++) {
        float s0, s1, x0, x1, y0, y1, z0, z1;
        up2(s0, s1, S[p]); up2(x0, x1, A0[p]); up2(y0, y1, A1[p]); up2(z0, z1, A2[p]);
        #pragma unroll
        for (int o = 16; o; o >>= 1) {
            s0 += __shfl_xor_sync(0xFFFFFFFFu, s0, o);
            x0 += __shfl_xor_sync(0xFFFFFFFFu, x0, o);
            y0 += __shfl_xor_sync(0xFFFFFFFFu, y0, o);
            z0 += __shfl_xor_sync(0xFFFFFFFFu, z0, o);
            s1 += __shfl_xor_sync(0xFFFFFFFFu, s1, o);
            x1 += __shfl_xor_sync(0xFFFFFFFFu, x1, o);
            y1 += __shfl_xor_sync(0xFFFFFFFFu, y1, o);
            z1 += __shfl_xor_sync(0xFFFFFFFFu, z1, o);
        }
        if (lane == 0) {
            float inv0, inv1;
            asm("rcp.approx.f32 %0, %1;" : "=f"(inv0) : "f"(s0));
            asm("rcp.approx.f32 %0, %1;" : "=f"(inv1) : "f"(s1));
            int row0 = rbase + 2*p;
            float* op0 = g_O + ((size_t)(b * L + row0) * H + h) * 3;
            float* op1 = g_O + ((size_t)(b * L + row0 + 1) * H + h) * 3;
            op0[0] = x0 * inv0; op0[1] = y0 * inv0; op0[2] = z0 * inv0;
            op1[0] = x1 * inv1; op1[1] = y1 * inv1; op1[2] = z1 * inv1;
        }
    }
}

// ============================================================
// K4: rotate back (R^T) + output GEMM (48 -> 1024) + bias, f32x2
// 16 tokens per block, 256 threads.  (proven R10)
// ============================================================
__global__ void __launch_bounds__(256) out_kernel(const float* __restrict__ rot,
                                                  const float* __restrict__ Wout,
                                                  const float* __restrict__ bout,
                                                  float* __restrict__ out)
{
    __shared__ float so[48][16];
    int t0  = blockIdx.x * 16;
    int tid = threadIdx.x;

    {
        int tt = tid >> 4, h = tid & 15;
        int t = t0 + tt;
        const float* op = g_O + ((size_t)t * H + h) * 3;
        float R0 = rot[t*9+0], R1 = rot[t*9+1], R2 = rot[t*9+2];
        float R3 = rot[t*9+3], R4 = rot[t*9+4], R5 = rot[t*9+5];
        float R6 = rot[t*9+6], R7 = rot[t*9+7], R8 = rot[t*9+8];
        float o0 = op[0], o1 = op[1], o2 = op[2];
        so[h*3+0][tt] = R0*o0 + R3*o1 + R6*o2;
        so[h*3+1][tt] = R1*o0 + R4*o1 + R7*o2;
        so[h*3+2][tt] = R2*o0 + R5*o1 + R8*o2;
    }
    __syncthreads();

    int e0 = tid;
    u64 acc[8][4];
    #pragma unroll
    for (int c = 0; c < 4; c++) {
        float bb = bout[e0 + 256*c];
        u64 bb2 = bc2(bb);
        #pragma unroll
        for (int tp = 0; tp < 8; tp++) acc[tp][c] = bb2;
    }

    #pragma unroll 4
    for (int k = 0; k < 48; k++) {
        u64 w2[4];
        #pragma unroll
        for (int c = 0; c < 4; c++) w2[c] = bc2(Wout[(size_t)k*E + e0 + 256*c]);
        const u64* sop = (const u64*)&so[k][0];
        #pragma unroll
        for (int tp = 0; tp < 8; tp++) {
            u64 sv = sop[tp];
            acc[tp][0] = fma2(sv, w2[0], acc[tp][0]);
            acc[tp][1] = fma2(sv, w2[1], acc[tp][1]);
            acc[tp][2] = fma2(sv, w2[2], acc[tp][2]);
            acc[tp][3] = fma2(sv, w2[3], acc[tp][3]);
        }
    }
    #pragma unroll
    for (int tp = 0; tp < 8; tp++) {
        float* orow0 = out + (size_t)(t0 + 2*tp) * E;
        float* orow1 = out + (size_t)(t0 + 2*tp + 1) * E;
        #pragma unroll
        for (int c = 0; c < 4; c++) {
            float lo, hi;
            up2(lo, hi, acc[tp][c]);
            orow0[e0 + 256*c] = lo;
            orow1[e0 + 256*c] = hi;
        }
    }
}

// ============================================================
extern "C" void kernel_launch(void* const* d_in, const int* in_sizes, int n_in,
                              void* d_out, int out_size)
{
    const float*         x       = (const float*)d_in[0];
    const float*         rot     = (const float*)d_in[1];
    const float*         trans   = (const float*)d_in[2];
    const unsigned char* mask    = (const unsigned char*)d_in[3];
    const float*         Wqkv    = (const float*)d_in[4];
    const float*         Wout    = (const float*)d_in[5];
    const float*         bout    = (const float*)d_in[6];
    const float*         gamma   = (const float*)d_in[7];
    const float*         beta    = (const float*)d_in[8];
    const float*         r_scale = (const float*)d_in[9];
    const float*         d_scale = (const float*)d_in[10];
    float* out = (float*)d_out;

    ln_stats<<<NT/8, 256>>>(x);
    qkv_gemm<<<dim3(NT/64, 5, KSPLIT), 128>>>(x, gamma, beta, Wqkv);
    pack_kernel<<<(NT*H + 255)/256, 256>>>(rot, trans, mask, r_scale, d_scale);
    attn_kernel<<<dim3(B*H, L/32), 256>>>();
    out_kernel<<<NT/16, 256>>>(rot, Wout, bout, out);
}

// round 14
// speedup vs baseline: 1.1790x; 1.0293x over previous
#include <cuda_runtime.h>
#include <cuda_bf16.h>
#include <math_constants.h>

// Problem constants
#define B 2
#define L 1024
#define E 1024
#define H 16
#define NT (B*L)          // 2048 tokens
#define LOG2E 1.4426950408889634f
#define KSPLIT 4

typedef unsigned long long u64;

// -------- scratch (static __device__, no allocations) --------
__device__ float2 g_stats[NT];                   // per-token (mu, rstd)
__device__ float  g_projp[KSPLIT][NT * 240];     // QKV projection partials
__device__ float4 g_Q[B*H*L * 2];                // per (b,h,i): (alpha'*Qr, q2), (qd, -beta')
__device__ float4 g_K[B*H*L * 3];                // per (b,h,j): (Kr, k2), (-2kd, maskpen'), (V, 0)
__device__ float  g_O[NT * H * 3];               // attention output (B,L,H,3)

// ---------------- f32x2 helpers ----------------
__device__ __forceinline__ u64 pk2(float lo, float hi)
{ u64 r; asm("mov.b64 %0, {%1,%2};" : "=l"(r) : "f"(lo), "f"(hi)); return r; }
__device__ __forceinline__ u64 bc2(float v) { return pk2(v, v); }
__device__ __forceinline__ void up2(float &lo, float &hi, u64 v)
{ asm("mov.b64 {%0,%1}, %2;" : "=f"(lo), "=f"(hi) : "l"(v)); }
__device__ __forceinline__ u64 fma2(u64 a, u64 b, u64 c)
{ u64 d; asm("fma.rn.f32x2 %0, %1, %2, %3;" : "=l"(d) : "l"(a), "l"(b), "l"(c)); return d; }
__device__ __forceinline__ u64 add2(u64 a, u64 b)
{ u64 d; asm("add.rn.f32x2 %0, %1, %2;" : "=l"(d) : "l"(a), "l"(b)); return d; }

// ============================================================
// K1: LayerNorm STATS, warp-per-token (8 tokens/block, no smem)
// ============================================================
__global__ void __launch_bounds__(256) ln_stats(const float* __restrict__ x)
{
    int warp = threadIdx.x >> 5, lane = threadIdx.x & 31;
    int t = blockIdx.x * 8 + warp;
    const float4* xr = (const float4*)(x + (size_t)t * E);
    float s = 0.f, ss = 0.f;
    #pragma unroll
    for (int i = 0; i < 8; i++) {
        float4 v = xr[lane + 32 * i];
        s  += v.x + v.y + v.z + v.w;
        ss += v.x*v.x + v.y*v.y + v.z*v.z + v.w*v.w;
    }
    #pragma unroll
    for (int o = 16; o; o >>= 1) {
        s  += __shfl_xor_sync(0xFFFFFFFFu, s,  o);
        ss += __shfl_xor_sync(0xFFFFFFFFu, ss, o);
    }
    if (lane == 0) {
        float mu  = s * (1.0f / E);
        float var = ss * (1.0f / E) - mu * mu;
        g_stats[t] = make_float2(mu, rsqrtf(var + 1e-5f));
    }
}

// ============================================================
// K2: QKV GEMM, f32x2, conflict-free staging, LN fused,
// register-prefetch double-buffered pipeline (1 sync/tile).
// ============================================================
__global__ void __launch_bounds__(128) qkv_gemm(const float* __restrict__ x,
                                                const float* __restrict__ gamma,
                                                const float* __restrict__ beta,
                                                const float* __restrict__ W)
{
#if __CUDA_ARCH__ >= 900
    cudaGridDependencySynchronize();
#endif
    __shared__ float As[2][16 * 64];   // 2 x 4KB
    __shared__ float Bs[2][16 * 98];   // 2 x 6.27KB

    int bm = blockIdx.x * 64;
    int bn = blockIdx.y * 48;
    int kh = blockIdx.z;
    int t  = threadIdx.x;
    int ty2 = (t >> 4) * 2;
    int tx = t & 15;

    u64 acc[4][3];
    #pragma unroll
    for (int i = 0; i < 4; i++)
        #pragma unroll
        for (int c = 0; c < 3; c++) acc[i][c] = 0ull;

    int arow = t >> 2;
    int akc  = (t & 3) * 4;
    int aq2  = (t & 3) << 1;
    int bk   = t >> 3;
    int bcf  = (t & 7) * 6;

    const float* xp0 = x + (size_t)(bm + arow) * E + akc;
    const float* xp1 = x + (size_t)(bm + arow + 32) * E + akc;
    const float* wpb = W + (size_t)bk * 240 + bn + bcf;

    float2 st0 = g_stats[bm + arow];
    float2 st1 = g_stats[bm + arow + 32];

    int gofs0 = (((arow >> 2)        ^ aq2) << 2) + (arow & 3);
    int gofs1 = ((((arow + 32) >> 2) ^ aq2) << 2) + ((arow + 32) & 3);

    const int k0base = kh * (1024 / KSPLIT);
    const int NTILE = (1024 / KSPLIT) / 16;

    float4 av0, av1, ga, bt;
    float2 b0, b1, b2;

    {
        int k0 = k0base;
        av0 = *(const float4*)(xp0 + k0);
        av1 = *(const float4*)(xp1 + k0);
        ga  = *(const float4*)(gamma + k0 + akc);
        bt  = *(const float4*)(beta  + k0 + akc);
        const float* wp = wpb + (size_t)k0 * 240;
        b0 = *(const float2*)(wp + 0);
        b1 = *(const float2*)(wp + 2);
        b2 = *(const float2*)(wp + 4);
    }
    {
        float* A = As[0];
        float mu = st0.x, rs = st0.y;
        A[(akc + 0) * 64 + gofs0] = fmaf((av0.x - mu) * rs, ga.x, bt.x);
        A[(akc + 1) * 64 + gofs0] = fmaf((av0.y - mu) * rs, ga.y, bt.y);
        A[(akc + 2) * 64 + gofs0] = fmaf((av0.z - mu) * rs, ga.z, bt.z);
        A[(akc + 3) * 64 + gofs0] = fmaf((av0.w - mu) * rs, ga.w, bt.w);
        mu = st1.x; rs = st1.y;
        A[(akc + 0) * 64 + gofs1] = fmaf((av1.x - mu) * rs, ga.x, bt.x);
        A[(akc + 1) * 64 + gofs1] = fmaf((av1.y - mu) * rs, ga.y, bt.y);
        A[(akc + 2) * 64 + gofs1] = fmaf((av1.z - mu) * rs, ga.z, bt.z);
        A[(akc + 3) * 64 + gofs1] = fmaf((av1.w - mu) * rs, ga.w, bt.w);
        u64* bs = (u64*)&Bs[0][bk * 98 + bcf * 2];
        bs[0] = bc2(b0.x); bs[1] = bc2(b0.y);
        bs[2] = bc2(b1.x); bs[3] = bc2(b1.y);
        bs[4] = bc2(b2.x); bs[5] = bc2(b2.y);
    }
    __syncthreads();

    for (int it = 0; it < NTILE; it++) {
        if (it + 1 < NTILE) {
            int kn = k0base + (it + 1) * 16;
            av0 = *(const float4*)(xp0 + kn);
            av1 = *(const float4*)(xp1 + kn);
            ga  = *(const float4*)(gamma + kn + akc);
            bt  = *(const float4*)(beta  + kn + akc);
            const float* wp = wpb + (size_t)kn * 240;
            b0 = *(const float2*)(wp + 0);
            b1 = *(const float2*)(wp + 2);
            b2 = *(const float2*)(wp + 4);
        }

        const float* Ab = As[it & 1];
        const float* Bb = Bs[it & 1];
        #pragma unroll
        for (int kk = 0; kk < 16; kk++) {
            const int q2s = (kk >> 2) << 1;
            const float* arow_p = &Ab[kk * 64 + ((ty2 ^ q2s) << 2)];
            ulonglong2 a01 = *(const ulonglong2*)(arow_p);
            ulonglong2 a23 = *(const ulonglong2*)(arow_p + 4);
            const float* brow = &Bb[kk * 98 + tx * 6];
            u64 w0 = *(const u64*)(brow + 0);
            u64 w1 = *(const u64*)(brow + 2);
            u64 w2 = *(const u64*)(brow + 4);
            acc[0][0]=fma2(a01.x,w0,acc[0][0]); acc[0][1]=fma2(a01.x,w1,acc[0][1]); acc[0][2]=fma2(a01.x,w2,acc[0][2]);
            acc[1][0]=fma2(a01.y,w0,acc[1][0]); acc[1][1]=fma2(a01.y,w1,acc[1][1]); acc[1][2]=fma2(a01.y,w2,acc[1][2]);
            acc[2][0]=fma2(a23.x,w0,acc[2][0]); acc[2][1]=fma2(a23.x,w1,acc[2][1]); acc[2][2]=fma2(a23.x,w2,acc[2][2]);
            acc[3][0]=fma2(a23.y,w0,acc[3][0]); acc[3][1]=fma2(a23.y,w1,acc[3][1]); acc[3][2]=fma2(a23.y,w2,acc[3][2]);
        }

        if (it + 1 < NTILE) {
            int nb = (it + 1) & 1;
            float* A = As[nb];
            float mu = st0.x, rs = st0.y;
            A[(akc + 0) * 64 + gofs0] = fmaf((av0.x - mu) * rs, ga.x, bt.x);
            A[(akc + 1) * 64 + gofs0] = fmaf((av0.y - mu) * rs, ga.y, bt.y);
            A[(akc + 2) * 64 + gofs0] = fmaf((av0.z - mu) * rs, ga.z, bt.z);
            A[(akc + 3) * 64 + gofs0] = fmaf((av0.w - mu) * rs, ga.w, bt.w);
            mu = st1.x; rs = st1.y;
            A[(akc + 0) * 64 + gofs1] = fmaf((av1.x - mu) * rs, ga.x, bt.x);
            A[(akc + 1) * 64 + gofs1] = fmaf((av1.y - mu) * rs, ga.y, bt.y);
            A[(akc + 2) * 64 + gofs1] = fmaf((av1.z - mu) * rs, ga.z, bt.z);
            A[(akc + 3) * 64 + gofs1] = fmaf((av1.w - mu) * rs, ga.w, bt.w);
            u64* bs = (u64*)&Bs[nb][bk * 98 + bcf * 2];
            bs[0] = bc2(b0.x); bs[1] = bc2(b0.y);
            bs[2] = bc2(b1.x); bs[3] = bc2(b1.y);
            bs[4] = bc2(b2.x); bs[5] = bc2(b2.y);
            __syncthreads();
        }
    }

    float* out = g_projp[kh];
    int ty = t >> 4;
    #pragma unroll
    for (int i = 0; i < 4; i++) {
        int row = bm + ty * 8 + 2 * i;
        #pragma unroll
        for (int c = 0; c < 3; c++) {
            float lo, hi;
            up2(lo, hi, acc[i][c]);
            int col = bn + tx * 3 + c;
            out[(size_t)row * 240 + col]       = lo;
            out[(size_t)(row + 1) * 240 + col] = hi;
        }
    }
}

// ============================================================
// K2b: rotate + translate + pack per (token, head)
// ============================================================
__device__ __forceinline__ float softplus_f(float x)
{
    return (x > 20.f) ? x : log1pf(__expf(x));
}

__global__ void __launch_bounds__(256) pack_kernel(const float* __restrict__ rot,
                                                   const float* __restrict__ trans,
                                                   const unsigned char* __restrict__ mask,
                                                   const float* __restrict__ r_scale,
                                                   const float* __restrict__ d_scale)
{
#if __CUDA_ARCH__ >= 900
    cudaGridDependencySynchronize();
#endif
    int gid = blockIdx.x * blockDim.x + threadIdx.x;
    if (gid >= NT * H) return;
    int t = gid >> 4;
    int h = gid & 15;

    float R[9];
    #pragma unroll
    for (int i = 0; i < 9; i++) R[i] = rot[t*9 + i];
    float T0 = trans[t*3+0], T1 = trans[t*3+1], T2 = trans[t*3+2];

    float y[5][3];
    #pragma unroll
    for (int f = 0; f < 5; f++) {
        int o = f*48 + h*3;
        float v0 = 0.f, v1 = 0.f, v2 = 0.f;
        #pragma unroll
        for (int q = 0; q < KSPLIT; q++) {
            const float* P = g_projp[q] + (size_t)t * 240;
            v0 += P[o+0]; v1 += P[o+1]; v2 += P[o+2];
        }
        y[f][0] = R[0]*v0 + R[1]*v1 + R[2]*v2;
        y[f][1] = R[3]*v0 + R[4]*v1 + R[5]*v2;
        y[f][2] = R[6]*v0 + R[7]*v1 + R[8]*v2;
    }
    const float scale = 0.5773502691896258f;      // 3^-0.5
    float alpha = softplus_f(r_scale[h]) * scale * LOG2E;
    float nbeta = -softplus_f(d_scale[h]) * scale * LOG2E;

    float qd0 = y[2][0] + T0, qd1 = y[2][1] + T1, qd2 = y[2][2] + T2;
    float q2  = qd0*qd0 + qd1*qd1 + qd2*qd2;
    float kd0 = y[3][0] + T0, kd1 = y[3][1] + T1, kd2 = y[3][2] + T2;
    float k2  = kd0*kd0 + kd1*kd1 + kd2*kd2;

    int b = t >> 10, l = t & 1023;
    int base = (b*H + h) * L + l;

    g_Q[base*2 + 0] = make_float4(alpha*y[0][0], alpha*y[0][1], alpha*y[0][2], q2);
    g_Q[base*2 + 1] = make_float4(qd0, qd1, qd2, nbeta);

    float mpen = mask[t] ? -2.0e9f : 0.f;   // log2 units; EX2 -> 0
    g_K[base*3 + 0] = make_float4(y[1][0], y[1][1], y[1][2], k2);
    g_K[base*3 + 1] = make_float4(-2.f*kd0, -2.f*kd1, -2.f*kd2, mpen);
    g_K[base*3 + 2] = make_float4(y[4][0], y[4][1], y[4][2], 0.f);
}

// ============================================================
// K3: flash attention, row-pair f32x2, no online max.  (proven R10)
// 8 warps x 4 rows; grid (B*H, L/32); 4 blocks/SM (regs 64).
// ============================================================
__global__ void __launch_bounds__(256, 4) attn_kernel()
{
#if __CUDA_ARCH__ >= 900
    cudaGridDependencySynchronize();
#endif
    __shared__ float4 sk[L * 3];   // 49152 bytes

    int bh    = blockIdx.x;
    int itile = blockIdx.y;

    const float4* Ksrc = g_K + (size_t)bh * L * 3;
    #pragma unroll
    for (int i = 0; i < 12; i++) sk[threadIdx.x + 256 * i] = Ksrc[threadIdx.x + 256 * i];
    __syncthreads();

    int warp = threadIdx.x >> 5, lane = threadIdx.x & 31;
    int rbase = itile * 32 + warp * 4;

    const float4* Qsrc = g_Q + (size_t)(bh * L + rbase) * 2;
    u64 QRX[2], QRY[2], QRZ[2], Q2[2], QDX[2], QDY[2], QDZ[2];
    u64 S[2], A0[2], A1[2], A2[2];
    u64 NB;
    #pragma unroll
    for (int p = 0; p < 2; p++) {
        float4 alo = Qsrc[(2*p)*2],     blo = Qsrc[(2*p)*2 + 1];
        float4 ahi = Qsrc[(2*p+1)*2],   bhi = Qsrc[(2*p+1)*2 + 1];
        QRX[p] = pk2(alo.x, ahi.x); QRY[p] = pk2(alo.y, ahi.y);
        QRZ[p] = pk2(alo.z, ahi.z); Q2 [p] = pk2(alo.w, ahi.w);
        QDX[p] = pk2(blo.x, bhi.x); QDY[p] = pk2(blo.y, bhi.y);
        QDZ[p] = pk2(blo.z, bhi.z);
        if (p == 0) NB = bc2(blo.w);
        S[p] = 0ull; A0[p] = 0ull; A1[p] = 0ull; A2[p] = 0ull;
    }

    #pragma unroll 4
    for (int jj = 0; jj < 32; jj++) {
        int j = jj * 32 + lane;
        float4 kr = sk[j*3 + 0];
        float4 kd = sk[j*3 + 1];
        float4 vv = sk[j*3 + 2];
        u64 KRX = bc2(kr.x), KRY = bc2(kr.y), KRZ = bc2(kr.z), KRW = bc2(kr.w);
        u64 KDX = bc2(kd.x), KDY = bc2(kd.y), KDZ = bc2(kd.z), KDW = bc2(kd.w);
        u64 VX  = bc2(vv.x), VY  = bc2(vv.y), VZ  = bc2(vv.z);
        #pragma unroll
        for (int p = 0; p < 2; p++) {
            u64 t1 = fma2(QRX[p], KRX, KDW);
            t1 = fma2(QRY[p], KRY, t1);
            t1 = fma2(QRZ[p], KRZ, t1);
            u64 d2 = add2(Q2[p], KRW);
            d2 = fma2(QDX[p], KDX, d2);
            d2 = fma2(QDY[p], KDY, d2);
            d2 = fma2(QDZ[p], KDZ, d2);
            float d2a, d2b;
            up2(d2a, d2b, d2);
            float da, db, pa, pb;
            float ada = fabsf(d2a), adb = fabsf(d2b);
            asm("sqrt.approx.f32 %0, %1;" : "=f"(da) : "f"(ada));
            asm("sqrt.approx.f32 %0, %1;" : "=f"(db) : "f"(adb));
            u64 DD = pk2(da, db);
            u64 ARG = fma2(NB, DD, t1);
            float arga, argb;
            up2(arga, argb, ARG);
            asm("ex2.approx.f32 %0, %1;" : "=f"(pa) : "f"(arga));
            asm("ex2.approx.f32 %0, %1;" : "=f"(pb) : "f"(argb));
            u64 P = pk2(pa, pb);
            S [p] = add2(S[p], P);
            A0[p] = fma2(P, VX, A0[p]);
            A1[p] = fma2(P, VY, A1[p]);
            A2[p] = fma2(P, VZ, A2[p]);
        }
    }

    int b = bh >> 4, h = bh & 15;
    #pragma unroll
    for (int p = 0; p < 2; p++) {
        float s0, s1, x0, x1, y0, y1, z0, z1;
        up2(s0, s1, S[p]); up2(x0, x1, A0[p]); up2(y0, y1, A1[p]); up2(z0, z1, A2[p]);
        #pragma unroll
        for (int o = 16; o; o >>= 1) {
            s0 += __shfl_xor_sync(0xFFFFFFFFu, s0, o);
            x0 += __shfl_xor_sync(0xFFFFFFFFu, x0, o);
            y0 += __shfl_xor_sync(0xFFFFFFFFu, y0, o);
            z0 += __shfl_xor_sync(0xFFFFFFFFu, z0, o);
            s1 += __shfl_xor_sync(0xFFFFFFFFu, s1, o);
            x1 += __shfl_xor_sync(0xFFFFFFFFu, x1, o);
            y1 += __shfl_xor_sync(0xFFFFFFFFu, y1, o);
            z1 += __shfl_xor_sync(0xFFFFFFFFu, z1, o);
        }
        if (lane == 0) {
            float inv0, inv1;
            asm("rcp.approx.f32 %0, %1;" : "=f"(inv0) : "f"(s0));
            asm("rcp.approx.f32 %0, %1;" : "=f"(inv1) : "f"(s1));
            int row0 = rbase + 2*p;
            float* op0 = g_O + ((size_t)(b * L + row0) * H + h) * 3;
            float* op1 = g_O + ((size_t)(b * L + row0 + 1) * H + h) * 3;
            op0[0] = x0 * inv0; op0[1] = y0 * inv0; op0[2] = z0 * inv0;
            op1[0] = x1 * inv1; op1[1] = y1 * inv1; op1[2] = z1 * inv1;
        }
    }
}

// ============================================================
// K4: rotate back (R^T) + output GEMM (48 -> 1024) + bias, f32x2
// 16 tokens per block, 256 threads.  (proven R10)
// ============================================================
__global__ void __launch_bounds__(256) out_kernel(const float* __restrict__ rot,
                                                  const float* __restrict__ Wout,
                                                  const float* __restrict__ bout,
                                                  float* __restrict__ out)
{
#if __CUDA_ARCH__ >= 900
    cudaGridDependencySynchronize();
#endif
    __shared__ float so[48][16];
    int t0  = blockIdx.x * 16;
    int tid = threadIdx.x;

    {
        int tt = tid >> 4, h = tid & 15;
        int t = t0 + tt;
        const float* op = g_O + ((size_t)t * H + h) * 3;
        float R0 = rot[t*9+0], R1 = rot[t*9+1], R2 = rot[t*9+2];
        float R3 = rot[t*9+3], R4 = rot[t*9+4], R5 = rot[t*9+5];
        float R6 = rot[t*9+6], R7 = rot[t*9+7], R8 = rot[t*9+8];
        float o0 = op[0], o1 = op[1], o2 = op[2];
        so[h*3+0][tt] = R0*o0 + R3*o1 + R6*o2;
        so[h*3+1][tt] = R1*o0 + R4*o1 + R7*o2;
        so[h*3+2][tt] = R2*o0 + R5*o1 + R8*o2;
    }
    __syncthreads();

    int e0 = tid;
    u64 acc[8][4];
    #pragma unroll
    for (int c = 0; c < 4; c++) {
        float bb = bout[e0 + 256*c];
        u64 bb2 = bc2(bb);
        #pragma unroll
        for (int tp = 0; tp < 8; tp++) acc[tp][c] = bb2;
    }

    #pragma unroll 4
    for (int k = 0; k < 48; k++) {
        u64 w2[4];
        #pragma unroll
        for (int c = 0; c < 4; c++) w2[c] = bc2(Wout[(size_t)k*E + e0 + 256*c]);
        const u64* sop = (const u64*)&so[k][0];
        #pragma unroll
        for (int tp = 0; tp < 8; tp++) {
            u64 sv = sop[tp];
            acc[tp][0] = fma2(sv, w2[0], acc[tp][0]);
            acc[tp][1] = fma2(sv, w2[1], acc[tp][1]);
            acc[tp][2] = fma2(sv, w2[2], acc[tp][2]);
            acc[tp][3] = fma2(sv, w2[3], acc[tp][3]);
        }
    }
    #pragma unroll
    for (int tp = 0; tp < 8; tp++) {
        float* orow0 = out + (size_t)(t0 + 2*tp) * E;
        float* orow1 = out + (size_t)(t0 + 2*tp + 1) * E;
        #pragma unroll
        for (int c = 0; c < 4; c++) {
            float lo, hi;
            up2(lo, hi, acc[tp][c]);
            orow0[e0 + 256*c] = lo;
            orow1[e0 + 256*c] = hi;
        }
    }
}

// ============================================================
// PDL launch helpers
// ============================================================
template <typename F, typename... Args>
static void launch_pdl(F func, dim3 grid, dim3 block, Args... args)
{
    cudaLaunchConfig_t cfg = {};
    cfg.gridDim = grid;
    cfg.blockDim = block;
    cfg.dynamicSmemBytes = 0;
    cfg.stream = 0;
    cudaLaunchAttribute attr[1];
    attr[0].id = cudaLaunchAttributeProgrammaticStreamSerialization;
    attr[0].val.programmaticStreamSerializationAllowed = 1;
    cfg.attrs = attr;
    cfg.numAttrs = 1;
    cudaLaunchKernelEx(&cfg, func, args...);
}

// ============================================================
extern "C" void kernel_launch(void* const* d_in, const int* in_sizes, int n_in,
                              void* d_out, int out_size)
{
    const float*         x       = (const float*)d_in[0];
    const float*         rot     = (const float*)d_in[1];
    const float*         trans   = (const float*)d_in[2];
    const unsigned char* mask    = (const unsigned char*)d_in[3];
    const float*         Wqkv    = (const float*)d_in[4];
    const float*         Wout    = (const float*)d_in[5];
    const float*         bout    = (const float*)d_in[6];
    const float*         gamma   = (const float*)d_in[7];
    const float*         beta    = (const float*)d_in[8];
    const float*         r_scale = (const float*)d_in[9];
    const float*         d_scale = (const float*)d_in[10];
    float* out = (float*)d_out;

    ln_stats<<<NT/8, 256>>>(x);
    launch_pdl(qkv_gemm, dim3(NT/64, 5, KSPLIT), dim3(128), x, gamma, beta, Wqkv);
    launch_pdl(pack_kernel, dim3((NT*H + 255)/256), dim3(256), rot, trans, mask, r_scale, d_scale);
    launch_pdl(attn_kernel, dim3(B*H, L/32), dim3(256));
    launch_pdl(out_kernel, dim3(NT/16), dim3(256), rot, Wout, bout, out);
}

// round 15
// speedup vs baseline: 1.1981x; 1.0163x over previous
#include <cuda_runtime.h>
#include <cuda_bf16.h>
#include <math_constants.h>

// Problem constants
#define B 2
#define L 1024
#define E 1024
#define H 16
#define NT (B*L)          // 2048 tokens
#define LOG2E 1.4426950408889634f
#define KSPLIT 4

typedef unsigned long long u64;

// -------- scratch (static __device__, no allocations) --------
__device__ float2 g_stats[NT];                   // per-token (mu, rstd)
__device__ float  g_projp[KSPLIT][NT * 240];     // QKV projection partials
__device__ float4 g_Q[B*H*L * 2];                // per (b,h,i): (alpha'*Qr, q2), (qd, -beta')
__device__ float4 g_K[B*H*L * 3];                // per (b,h,j): (Kr, k2), (-2kd, maskpen'), (V, 0)
__device__ float  g_O[NT * H * 3];               // attention output (B,L,H,3)

// ---------------- f32x2 helpers ----------------
__device__ __forceinline__ u64 pk2(float lo, float hi)
{ u64 r; asm("mov.b64 %0, {%1,%2};" : "=l"(r) : "f"(lo), "f"(hi)); return r; }
__device__ __forceinline__ u64 bc2(float v) { return pk2(v, v); }
__device__ __forceinline__ void up2(float &lo, float &hi, u64 v)
{ asm("mov.b64 {%0,%1}, %2;" : "=f"(lo), "=f"(hi) : "l"(v)); }
__device__ __forceinline__ u64 fma2(u64 a, u64 b, u64 c)
{ u64 d; asm("fma.rn.f32x2 %0, %1, %2, %3;" : "=l"(d) : "l"(a), "l"(b), "l"(c)); return d; }
__device__ __forceinline__ u64 add2(u64 a, u64 b)
{ u64 d; asm("add.rn.f32x2 %0, %1, %2;" : "=l"(d) : "l"(a), "l"(b)); return d; }

// ============================================================
// K1: LayerNorm STATS, warp-per-token (8 tokens/block, no smem)
// ============================================================
__global__ void __launch_bounds__(256) ln_stats(const float* __restrict__ x)
{
    int warp = threadIdx.x >> 5, lane = threadIdx.x & 31;
    int t = blockIdx.x * 8 + warp;
    const float4* xr = (const float4*)(x + (size_t)t * E);
    float s = 0.f, ss = 0.f;
    #pragma unroll
    for (int i = 0; i < 8; i++) {
        float4 v = xr[lane + 32 * i];
        s  += v.x + v.y + v.z + v.w;
        ss += v.x*v.x + v.y*v.y + v.z*v.z + v.w*v.w;
    }
    #pragma unroll
    for (int o = 16; o; o >>= 1) {
        s  += __shfl_xor_sync(0xFFFFFFFFu, s,  o);
        ss += __shfl_xor_sync(0xFFFFFFFFu, ss, o);
    }
    if (lane == 0) {
        float mu  = s * (1.0f / E);
        float var = ss * (1.0f / E) - mu * mu;
        g_stats[t] = make_float2(mu, rsqrtf(var + 1e-5f));
    }
}

// ============================================================
// K2: QKV GEMM, f32x2, conflict-free staging, LN fused,
// register-prefetch double-buffered pipeline, PDL with
// pre-sync independent prefetch of tile 0.
// ============================================================
__global__ void __launch_bounds__(128) qkv_gemm(const float* __restrict__ x,
                                                const float* __restrict__ gamma,
                                                const float* __restrict__ beta,
                                                const float* __restrict__ W)
{
    __shared__ float As[2][16 * 64];   // 2 x 4KB
    __shared__ float Bs[2][16 * 98];   // 2 x 6.27KB

    int bm = blockIdx.x * 64;
    int bn = blockIdx.y * 48;
    int kh = blockIdx.z;
    int t  = threadIdx.x;
    int ty2 = (t >> 4) * 2;
    int tx = t & 15;

    u64 acc[4][3];
    #pragma unroll
    for (int i = 0; i < 4; i++)
        #pragma unroll
        for (int c = 0; c < 3; c++) acc[i][c] = 0ull;

    int arow = t >> 2;
    int akc  = (t & 3) * 4;
    int aq2  = (t & 3) << 1;
    int bk   = t >> 3;
    int bcf  = (t & 7) * 6;

    const float* xp0 = x + (size_t)(bm + arow) * E + akc;
    const float* xp1 = x + (size_t)(bm + arow + 32) * E + akc;
    const float* wpb = W + (size_t)bk * 240 + bn + bcf;

    int gofs0 = (((arow >> 2)        ^ aq2) << 2) + (arow & 3);
    int gofs1 = ((((arow + 32) >> 2) ^ aq2) << 2) + ((arow + 32) & 3);

    const int k0base = kh * (1024 / KSPLIT);
    const int NTILE = (1024 / KSPLIT) / 16;

    float4 av0, av1, ga, bt;
    float2 b0, b1, b2;

    // ---- PRE-SYNC: issue tile-0 loads (independent of ln_stats) ----
    {
        int k0 = k0base;
        av0 = *(const float4*)(xp0 + k0);
        av1 = *(const float4*)(xp1 + k0);
        ga  = *(const float4*)(gamma + k0 + akc);
        bt  = *(const float4*)(beta  + k0 + akc);
        const float* wp = wpb + (size_t)k0 * 240;
        b0 = *(const float2*)(wp + 0);
        b1 = *(const float2*)(wp + 2);
        b2 = *(const float2*)(wp + 4);
    }

#if __CUDA_ARCH__ >= 900
    cudaGridDependencySynchronize();
#endif
    float2 st0 = g_stats[bm + arow];
    float2 st1 = g_stats[bm + arow + 32];

    // ---- store tile 0 into buf 0 ----
    {
        float* A = As[0];
        float mu = st0.x, rs = st0.y;
        A[(akc + 0) * 64 + gofs0] = fmaf((av0.x - mu) * rs, ga.x, bt.x);
        A[(akc + 1) * 64 + gofs0] = fmaf((av0.y - mu) * rs, ga.y, bt.y);
        A[(akc + 2) * 64 + gofs0] = fmaf((av0.z - mu) * rs, ga.z, bt.z);
        A[(akc + 3) * 64 + gofs0] = fmaf((av0.w - mu) * rs, ga.w, bt.w);
        mu = st1.x; rs = st1.y;
        A[(akc + 0) * 64 + gofs1] = fmaf((av1.x - mu) * rs, ga.x, bt.x);
        A[(akc + 1) * 64 + gofs1] = fmaf((av1.y - mu) * rs, ga.y, bt.y);
        A[(akc + 2) * 64 + gofs1] = fmaf((av1.z - mu) * rs, ga.z, bt.z);
        A[(akc + 3) * 64 + gofs1] = fmaf((av1.w - mu) * rs, ga.w, bt.w);
        u64* bs = (u64*)&Bs[0][bk * 98 + bcf * 2];
        bs[0] = bc2(b0.x); bs[1] = bc2(b0.y);
        bs[2] = bc2(b1.x); bs[3] = bc2(b1.y);
        bs[4] = bc2(b2.x); bs[5] = bc2(b2.y);
    }
    __syncthreads();

    for (int it = 0; it < NTILE; it++) {
        if (it + 1 < NTILE) {
            int kn = k0base + (it + 1) * 16;
            av0 = *(const float4*)(xp0 + kn);
            av1 = *(const float4*)(xp1 + kn);
            ga  = *(const float4*)(gamma + kn + akc);
            bt  = *(const float4*)(beta  + kn + akc);
            const float* wp = wpb + (size_t)kn * 240;
            b0 = *(const float2*)(wp + 0);
            b1 = *(const float2*)(wp + 2);
            b2 = *(const float2*)(wp + 4);
        }

        const float* Ab = As[it & 1];
        const float* Bb = Bs[it & 1];
        #pragma unroll
        for (int kk = 0; kk < 16; kk++) {
            const int q2s = (kk >> 2) << 1;
            const float* arow_p = &Ab[kk * 64 + ((ty2 ^ q2s) << 2)];
            ulonglong2 a01 = *(const ulonglong2*)(arow_p);
            ulonglong2 a23 = *(const ulonglong2*)(arow_p + 4);
            const float* brow = &Bb[kk * 98 + tx * 6];
            u64 w0 = *(const u64*)(brow + 0);
            u64 w1 = *(const u64*)(brow + 2);
            u64 w2 = *(const u64*)(brow + 4);
            acc[0][0]=fma2(a01.x,w0,acc[0][0]); acc[0][1]=fma2(a01.x,w1,acc[0][1]); acc[0][2]=fma2(a01.x,w2,acc[0][2]);
            acc[1][0]=fma2(a01.y,w0,acc[1][0]); acc[1][1]=fma2(a01.y,w1,acc[1][1]); acc[1][2]=fma2(a01.y,w2,acc[1][2]);
            acc[2][0]=fma2(a23.x,w0,acc[2][0]); acc[2][1]=fma2(a23.x,w1,acc[2][1]); acc[2][2]=fma2(a23.x,w2,acc[2][2]);
            acc[3][0]=fma2(a23.y,w0,acc[3][0]); acc[3][1]=fma2(a23.y,w1,acc[3][1]); acc[3][2]=fma2(a23.y,w2,acc[3][2]);
        }

        if (it + 1 < NTILE) {
            int nb = (it + 1) & 1;
            float* A = As[nb];
            float mu = st0.x, rs = st0.y;
            A[(akc + 0) * 64 + gofs0] = fmaf((av0.x - mu) * rs, ga.x, bt.x);
            A[(akc + 1) * 64 + gofs0] = fmaf((av0.y - mu) * rs, ga.y, bt.y);
            A[(akc + 2) * 64 + gofs0] = fmaf((av0.z - mu) * rs, ga.z, bt.z);
            A[(akc + 3) * 64 + gofs0] = fmaf((av0.w - mu) * rs, ga.w, bt.w);
            mu = st1.x; rs = st1.y;
            A[(akc + 0) * 64 + gofs1] = fmaf((av1.x - mu) * rs, ga.x, bt.x);
            A[(akc + 1) * 64 + gofs1] = fmaf((av1.y - mu) * rs, ga.y, bt.y);
            A[(akc + 2) * 64 + gofs1] = fmaf((av1.z - mu) * rs, ga.z, bt.z);
            A[(akc + 3) * 64 + gofs1] = fmaf((av1.w - mu) * rs, ga.w, bt.w);
            u64* bs = (u64*)&Bs[nb][bk * 98 + bcf * 2];
            bs[0] = bc2(b0.x); bs[1] = bc2(b0.y);
            bs[2] = bc2(b1.x); bs[3] = bc2(b1.y);
            bs[4] = bc2(b2.x); bs[5] = bc2(b2.y);
            __syncthreads();
        }
    }

    float* out = g_projp[kh];
    int ty = t >> 4;
    #pragma unroll
    for (int i = 0; i < 4; i++) {
        int row = bm + ty * 8 + 2 * i;
        #pragma unroll
        for (int c = 0; c < 3; c++) {
            float lo, hi;
            up2(lo, hi, acc[i][c]);
            int col = bn + tx * 3 + c;
            out[(size_t)row * 240 + col]       = lo;
            out[(size_t)(row + 1) * 240 + col] = hi;
        }
    }
}

// ============================================================
// K2b: rotate + translate + pack per (token, head), PDL with
// pre-sync prefetch of rot/trans/mask/scales.
// Grid exact: NT*H/256 blocks.
// ============================================================
__device__ __forceinline__ float softplus_f(float x)
{
    return (x > 20.f) ? x : log1pf(__expf(x));
}

__global__ void __launch_bounds__(256) pack_kernel(const float* __restrict__ rot,
                                                   const float* __restrict__ trans,
                                                   const unsigned char* __restrict__ mask,
                                                   const float* __restrict__ r_scale,
                                                   const float* __restrict__ d_scale)
{
    int gid = blockIdx.x * blockDim.x + threadIdx.x;
    int t = gid >> 4;
    int h = gid & 15;

    // ---- PRE-SYNC: inputs independent of qkv ----
    float R[9];
    #pragma unroll
    for (int i = 0; i < 9; i++) R[i] = rot[t*9 + i];
    float T0 = trans[t*3+0], T1 = trans[t*3+1], T2 = trans[t*3+2];
    unsigned char mk = mask[t];
    const float scale = 0.5773502691896258f;      // 3^-0.5
    float alpha = softplus_f(r_scale[h]) * scale * LOG2E;
    float nbeta = -softplus_f(d_scale[h]) * scale * LOG2E;

#if __CUDA_ARCH__ >= 900
    cudaGridDependencySynchronize();
#endif

    float y[5][3];
    #pragma unroll
    for (int f = 0; f < 5; f++) {
        int o = f*48 + h*3;
        float v0 = 0.f, v1 = 0.f, v2 = 0.f;
        #pragma unroll
        for (int q = 0; q < KSPLIT; q++) {
            const float* P = g_projp[q] + (size_t)t * 240;
            v0 += P[o+0]; v1 += P[o+1]; v2 += P[o+2];
        }
        y[f][0] = R[0]*v0 + R[1]*v1 + R[2]*v2;
        y[f][1] = R[3]*v0 + R[4]*v1 + R[5]*v2;
        y[f][2] = R[6]*v0 + R[7]*v1 + R[8]*v2;
    }

    float qd0 = y[2][0] + T0, qd1 = y[2][1] + T1, qd2 = y[2][2] + T2;
    float q2  = qd0*qd0 + qd1*qd1 + qd2*qd2;
    float kd0 = y[3][0] + T0, kd1 = y[3][1] + T1, kd2 = y[3][2] + T2;
    float k2  = kd0*kd0 + kd1*kd1 + kd2*kd2;

    int b = t >> 10, l = t & 1023;
    int base = (b*H + h) * L + l;

    g_Q[base*2 + 0] = make_float4(alpha*y[0][0], alpha*y[0][1], alpha*y[0][2], q2);
    g_Q[base*2 + 1] = make_float4(qd0, qd1, qd2, nbeta);

    float mpen = mk ? -2.0e9f : 0.f;   // log2 units; EX2 -> 0
    g_K[base*3 + 0] = make_float4(y[1][0], y[1][1], y[1][2], k2);
    g_K[base*3 + 1] = make_float4(-2.f*kd0, -2.f*kd1, -2.f*kd2, mpen);
    g_K[base*3 + 2] = make_float4(y[4][0], y[4][1], y[4][2], 0.f);
}

// ============================================================
// K3: flash attention, row-pair f32x2, no online max.  (proven R10)
// 8 warps x 4 rows; grid (B*H, L/32); 4 blocks/SM (regs 64).
// ============================================================
__global__ void __launch_bounds__(256, 4) attn_kernel()
{
#if __CUDA_ARCH__ >= 900
    cudaGridDependencySynchronize();
#endif
    __shared__ float4 sk[L * 3];   // 49152 bytes

    int bh    = blockIdx.x;
    int itile = blockIdx.y;

    const float4* Ksrc = g_K + (size_t)bh * L * 3;
    #pragma unroll
    for (int i = 0; i < 12; i++) sk[threadIdx.x + 256 * i] = Ksrc[threadIdx.x + 256 * i];
    __syncthreads();

    int warp = threadIdx.x >> 5, lane = threadIdx.x & 31;
    int rbase = itile * 32 + warp * 4;

    const float4* Qsrc = g_Q + (size_t)(bh * L + rbase) * 2;
    u64 QRX[2], QRY[2], QRZ[2], Q2[2], QDX[2], QDY[2], QDZ[2];
    u64 S[2], A0[2], A1[2], A2[2];
    u64 NB;
    #pragma unroll
    for (int p = 0; p < 2; p++) {
        float4 alo = Qsrc[(2*p)*2],     blo = Qsrc[(2*p)*2 + 1];
        float4 ahi = Qsrc[(2*p+1)*2],   bhi = Qsrc[(2*p+1)*2 + 1];
        QRX[p] = pk2(alo.x, ahi.x); QRY[p] = pk2(alo.y, ahi.y);
        QRZ[p] = pk2(alo.z, ahi.z); Q2 [p] = pk2(alo.w, ahi.w);
        QDX[p] = pk2(blo.x, bhi.x); QDY[p] = pk2(blo.y, bhi.y);
        QDZ[p] = pk2(blo.z, bhi.z);
        if (p == 0) NB = bc2(blo.w);
        S[p] = 0ull; A0[p] = 0ull; A1[p] = 0ull; A2[p] = 0ull;
    }

    #pragma unroll 4
    for (int jj = 0; jj < 32; jj++) {
        int j = jj * 32 + lane;
        float4 kr = sk[j*3 + 0];
        float4 kd = sk[j*3 + 1];
        float4 vv = sk[j*3 + 2];
        u64 KRX = bc2(kr.x), KRY = bc2(kr.y), KRZ = bc2(kr.z), KRW = bc2(kr.w);
        u64 KDX = bc2(kd.x), KDY = bc2(kd.y), KDZ = bc2(kd.z), KDW = bc2(kd.w);
        u64 VX  = bc2(vv.x), VY  = bc2(vv.y), VZ  = bc2(vv.z);
        #pragma unroll
        for (int p = 0; p < 2; p++) {
            u64 t1 = fma2(QRX[p], KRX, KDW);
            t1 = fma2(QRY[p], KRY, t1);
            t1 = fma2(QRZ[p], KRZ, t1);
            u64 d2 = add2(Q2[p], KRW);
            d2 = fma2(QDX[p], KDX, d2);
            d2 = fma2(QDY[p], KDY, d2);
            d2 = fma2(QDZ[p], KDZ, d2);
            float d2a, d2b;
            up2(d2a, d2b, d2);
            float da, db, pa, pb;
            float ada = fabsf(d2a), adb = fabsf(d2b);
            asm("sqrt.approx.f32 %0, %1;" : "=f"(da) : "f"(ada));
            asm("sqrt.approx.f32 %0, %1;" : "=f"(db) : "f"(adb));
            u64 DD = pk2(da, db);
            u64 ARG = fma2(NB, DD, t1);
            float arga, argb;
            up2(arga, argb, ARG);
            asm("ex2.approx.f32 %0, %1;" : "=f"(pa) : "f"(arga));
            asm("ex2.approx.f32 %0, %1;" : "=f"(pb) : "f"(argb));
            u64 P = pk2(pa, pb);
            S [p] = add2(S[p], P);
            A0[p] = fma2(P, VX, A0[p]);
            A1[p] = fma2(P, VY, A1[p]);
            A2[p] = fma2(P, VZ, A2[p]);
        }
    }

    int b = bh >> 4, h = bh & 15;
    #pragma unroll
    for (int p = 0; p < 2; p++) {
        float s0, s1, x0, x1, y0, y1, z0, z1;
        up2(s0, s1, S[p]); up2(x0, x1, A0[p]); up2(y0, y1, A1[p]); up2(z0, z1, A2[p]);
        #pragma unroll
        for (int o = 16; o; o >>= 1) {
            s0 += __shfl_xor_sync(0xFFFFFFFFu, s0, o);
            x0 += __shfl_xor_sync(0xFFFFFFFFu, x0, o);
            y0 += __shfl_xor_sync(0xFFFFFFFFu, y0, o);
            z0 += __shfl_xor_sync(0xFFFFFFFFu, z0, o);
            s1 += __shfl_xor_sync(0xFFFFFFFFu, s1, o);
            x1 += __shfl_xor_sync(0xFFFFFFFFu, x1, o);
            y1 += __shfl_xor_sync(0xFFFFFFFFu, y1, o);
            z1 += __shfl_xor_sync(0xFFFFFFFFu, z1, o);
        }
        if (lane == 0) {
            float inv0, inv1;
            asm("rcp.approx.f32 %0, %1;" : "=f"(inv0) : "f"(s0));
            asm("rcp.approx.f32 %0, %1;" : "=f"(inv1) : "f"(s1));
            int row0 = rbase + 2*p;
            float* op0 = g_O + ((size_t)(b * L + row0) * H + h) * 3;
            float* op1 = g_O + ((size_t)(b * L + row0 + 1) * H + h) * 3;
            op0[0] = x0 * inv0; op0[1] = y0 * inv0; op0[2] = z0 * inv0;
            op1[0] = x1 * inv1; op1[1] = y1 * inv1; op1[2] = z1 * inv1;
        }
    }
}

// ============================================================
// K4: rotate back (R^T) + output GEMM (48 -> 1024) + bias, f32x2
// 16 tokens per block, 256 threads. PDL with pre-sync rot/bout loads.
// ============================================================
__global__ void __launch_bounds__(256) out_kernel(const float* __restrict__ rot,
                                                  const float* __restrict__ Wout,
                                                  const float* __restrict__ bout,
                                                  float* __restrict__ out)
{
    __shared__ float so[48][16];
    int t0  = blockIdx.x * 16;
    int tid = threadIdx.x;

    // ---- PRE-SYNC: rot + bout (independent of attn) ----
    int tt = tid >> 4, h = tid & 15;
    int t = t0 + tt;
    float R0 = rot[t*9+0], R1 = rot[t*9+1], R2 = rot[t*9+2];
    float R3 = rot[t*9+3], R4 = rot[t*9+4], R5 = rot[t*9+5];
    float R6 = rot[t*9+6], R7 = rot[t*9+7], R8 = rot[t*9+8];

    int e0 = tid;
    u64 acc[8][4];
    #pragma unroll
    for (int c = 0; c < 4; c++) {
        float bb = bout[e0 + 256*c];
        u64 bb2 = bc2(bb);
        #pragma unroll
        for (int tp = 0; tp < 8; tp++) acc[tp][c] = bb2;
    }

#if __CUDA_ARCH__ >= 900
    cudaGridDependencySynchronize();
#endif

    {
        const float* op = g_O + ((size_t)t * H + h) * 3;
        float o0 = op[0], o1 = op[1], o2 = op[2];
        so[h*3+0][tt] = R0*o0 + R3*o1 + R6*o2;
        so[h*3+1][tt] = R1*o0 + R4*o1 + R7*o2;
        so[h*3+2][tt] = R2*o0 + R5*o1 + R8*o2;
    }
    __syncthreads();

    #pragma unroll 4
    for (int k = 0; k < 48; k++) {
        u64 w2[4];
        #pragma unroll
        for (int c = 0; c < 4; c++) w2[c] = bc2(Wout[(size_t)k*E + e0 + 256*c]);
        const u64* sop = (const u64*)&so[k][0];
        #pragma unroll
        for (int tp = 0; tp < 8; tp++) {
            u64 sv = sop[tp];
            acc[tp][0] = fma2(sv, w2[0], acc[tp][0]);
            acc[tp][1] = fma2(sv, w2[1], acc[tp][1]);
            acc[tp][2] = fma2(sv, w2[2], acc[tp][2]);
            acc[tp][3] = fma2(sv, w2[3], acc[tp][3]);
        }
    }
    #pragma unroll
    for (int tp = 0; tp < 8; tp++) {
        float* orow0 = out + (size_t)(t0 + 2*tp) * E;
        float* orow1 = out + (size_t)(t0 + 2*tp + 1) * E;
        #pragma unroll
        for (int c = 0; c < 4; c++) {
            float lo, hi;
            up2(lo, hi, acc[tp][c]);
            orow0[e0 + 256*c] = lo;
            orow1[e0 + 256*c] = hi;
        }
    }
}

// ============================================================
// PDL launch helpers
// ============================================================
template <typename F, typename... Args>
static void launch_pdl(F func, dim3 grid, dim3 block, Args... args)
{
    cudaLaunchConfig_t cfg = {};
    cfg.gridDim = grid;
    cfg.blockDim = block;
    cfg.dynamicSmemBytes = 0;
    cfg.stream = 0;
    cudaLaunchAttribute attr[1];
    attr[0].id = cudaLaunchAttributeProgrammaticStreamSerialization;
    attr[0].val.programmaticStreamSerializationAllowed = 1;
    cfg.attrs = attr;
    cfg.numAttrs = 1;
    cudaLaunchKernelEx(&cfg, func, args...);
}

// ============================================================
extern "C" void kernel_launch(void* const* d_in, const int* in_sizes, int n_in,
                              void* d_out, int out_size)
{
    const float*         x       = (const float*)d_in[0];
    const float*         rot     = (const float*)d_in[1];
    const float*         trans   = (const float*)d_in[2];
    const unsigned char* mask    = (const unsigned char*)d_in[3];
    const float*         Wqkv    = (const float*)d_in[4];
    const float*         Wout    = (const float*)d_in[5];
    const float*         bout    = (const float*)d_in[6];
    const float*         gamma   = (const float*)d_in[7];
    const float*         beta    = (const float*)d_in[8];
    const float*         r_scale = (const float*)d_in[9];
    const float*         d_scale = (const float*)d_in[10];
    float* out = (float*)d_out;

    ln_stats<<<NT/8, 256>>>(x);
    launch_pdl(qkv_gemm, dim3(NT/64, 5, KSPLIT), dim3(128), x, gamma, beta, Wqkv);
    launch_pdl(pack_kernel, dim3((NT*H)/256), dim3(256), rot, trans, mask, r_scale, d_scale);
    launch_pdl(attn_kernel, dim3(B*H, L/32), dim3(256));
    launch_pdl(out_kernel, dim3(NT/16), dim3(256), rot, Wout, bout, out);
}